// round 7
// baseline (speedup 1.0000x reference)
#include <cuda_runtime.h>
#include <cstdint>

#define NXX 64
#define DTT 1e-4f

__device__ __forceinline__ float tanh_approx(float x) {
    float t;
    asm("tanh.approx.f32 %0, %1;" : "=f"(t) : "f"(x));
    return t;
}
__device__ __forceinline__ uint64_t pack2(float lo, float hi) {
    uint64_t r;
    asm("mov.b64 %0, {%1, %2};" : "=l"(r) : "f"(lo), "f"(hi));
    return r;
}
__device__ __forceinline__ void unpack2(uint64_t v, float& lo, float& hi) {
    asm("mov.b64 {%0, %1}, %2;" : "=f"(lo), "=f"(hi) : "l"(v));
}
__device__ __forceinline__ uint64_t fma2(uint64_t a, uint64_t b, uint64_t c) {
    uint64_t d;
    asm("fma.rn.f32x2 %0, %1, %2, %3;" : "=l"(d) : "l"(a), "l"(b), "l"(c));
    return d;
}
__device__ __forceinline__ uint64_t add2(uint64_t a, uint64_t b) {
    uint64_t d;
    asm("add.rn.f32x2 %0, %1, %2;" : "=l"(d) : "l"(a), "l"(b));
    return d;
}

// 128 threads: 2 lanes per grid point (p = tid>>1, s = tid&1).
// Lane s owns one full 16-unit layer, processed as 8 f32x2 PAIRS (FFMA2).
// Stencil folded into weights: z = Wp*up + Wm*um + zb,
//   Wp = 31.5*Wg + 3969*Wl, Wm = -31.5*Wg + 3969*Wl, Wuc = Wu - 7938*Wl
// (f64 folds at init; boundary lanes: Wp=Wm=0, Wuc=Wu).
// State stored DUPLICATED as float2 (u,u): one LDS.64 yields a ready
// broadcast-packed operand (no MOV-pack on the post-barrier path).
// zb/cb shadow work moved AFTER __syncthreads: BAR.SYNC.DEFER_BLOCKING does
// not block at issue, so the shadow runs inside the barrier-wait window and
// every warp ARRIVES ~40 cycles earlier (release earlier for all).
// Head fully folded: Cq = gamma*DT*wc; un = uc + DT*core + gamma*DT*bc + P.
__global__ __launch_bounds__(128, 1) void scct_kernel(
    const float* __restrict__ u0,  const float* __restrict__ w1,
    const float* __restrict__ b1,  const float* __restrict__ w2,
    const float* __restrict__ b2,  const float* __restrict__ wc,
    const float* __restrict__ bc,  const float* __restrict__ gamma_p,
    const int*   __restrict__ nt_p, float* __restrict__ out)
{
    __shared__ float2 ub2[2][NXX];

    const int tid = threadIdx.x;
    const int p = tid >> 1;   // grid point 0..63
    const int s = tid & 1;    // layer select

    const float* wsel = s ? w2 : w1;
    const float* bsel = s ? b2 : b1;

    const float gmm = *gamma_p;
    const float gdt = gmm * DTT;
    const bool interior = (p > 0) && (p < NXX - 1);

    uint64_t Wp2[8], Wm2[8], Wuc2[8], Bq2[8], Cq2[8];
#pragma unroll
    for (int j = 0; j < 8; j++) {
        float pl[2], ml[2], ul[2], bl[2], cl[2];
#pragma unroll
        for (int h = 0; h < 2; h++) {
            int q = 2 * j + h;
            double Wu = (double)wsel[q * 3 + 0];
            double Wg = (double)wsel[q * 3 + 1];
            double Wl = (double)wsel[q * 3 + 2];
            if (interior) {
                pl[h] = (float)( 31.5 * Wg + 3969.0 * Wl);
                ml[h] = (float)(-31.5 * Wg + 3969.0 * Wl);
                ul[h] = (float)(Wu - 7938.0 * Wl);
            } else {
                pl[h] = 0.0f;
                ml[h] = 0.0f;
                ul[h] = (float)Wu;
            }
            bl[h] = bsel[q];
            cl[h] = gdt * wc[s * 16 + q];
        }
        Wp2[j]  = pack2(pl[0], pl[1]);
        Wm2[j]  = pack2(ml[0], ml[1]);
        Wuc2[j] = pack2(ul[0], ul[1]);
        Bq2[j]  = pack2(bl[0], bl[1]);
        Cq2[j]  = pack2(cl[0], cl[1]);
    }
    const float Kc = gdt * (*bc);
    const int Nt = *nt_p;

    if (tid < NXX) {
        float v = u0[tid];
        ub2[0][tid] = make_float2(v, v);
    }
    __syncthreads();

    const float INVDX2 = 3969.0f;  // 63^2

    const int pm = (p == 0) ? 0 : p - 1;
    const int pp = (p == NXX - 1) ? NXX - 1 : p + 1;

    float uc = ub2[0][p].x;
    int cur = 0;

    // Initial shadow values from u0.
    uint64_t zb2[8];
    {
        uint64_t uc2 = pack2(uc, uc);
#pragma unroll
        for (int j = 0; j < 8; j++) zb2[j] = fma2(Wuc2[j], uc2, Bq2[j]);
    }
    float cb = fmaf(0.5f, uc, -(uc * uc * uc));   // 0.5u - u^3

#pragma unroll 2
    for (int it = 0; it < Nt; ++it) {
        const float2 umf = ub2[cur][pm];   // one LDS.64: packed (um, um)
        const float2 upf = ub2[cur][pp];   // one LDS.64: packed (up, up)
        const uint64_t um2 = pack2(umf.x, umf.y);  // register-pair alias (no-op movs)
        const uint64_t up2 = pack2(upf.x, upf.y);

        // 4 independent acc chains, depth 2 each.
        uint64_t A0 = 0ull, A1 = 0ull, A2 = 0ull, A3 = 0ull;
#pragma unroll
        for (int j = 0; j < 8; j++) {
            uint64_t z2 = fma2(Wp2[j], up2, fma2(Wm2[j], um2, zb2[j]));
            float zl, zh;
            unpack2(z2, zl, zh);
            uint64_t t2 = pack2(tanh_approx(zl), tanh_approx(zh));
            switch (j & 3) {
                case 0: A0 = fma2(Cq2[j], t2, A0); break;
                case 1: A1 = fma2(Cq2[j], t2, A1); break;
                case 2: A2 = fma2(Cq2[j], t2, A2); break;
                default: A3 = fma2(Cq2[j], t2, A3); break;
            }
        }
        float al, ah;
        unpack2(add2(add2(A0, A1), add2(A2, A3)), al, ah);
        float P = al + ah;
        P += __shfl_xor_sync(0xffffffffu, P, 1);   // both lanes: full head sum

        // core/base overlap the shfl
        const float um = umf.x, up = upf.x;
        const float lx   = ((up - 2.0f * uc) + um) * INVDX2;
        const float core = fmaf(0.8f, lx, cb);
        const float base = fmaf(DTT, core, uc) + Kc;

        float un = base + P;
        un = interior ? un : 0.0f;

        if (s == 0) ub2[cur ^ 1][p] = make_float2(un, un);
        __syncthreads();

        // ---- shadow AFTER the barrier: overlaps the barrier-wait window ----
        {
            uint64_t un2 = pack2(un, un);
#pragma unroll
            for (int j = 0; j < 8; j++) zb2[j] = fma2(Wuc2[j], un2, Bq2[j]);
        }
        cb = fmaf(0.5f, un, -(un * un * un));

        uc = un;
        cur ^= 1;
    }

    // ---- epilogue: u, phi2, entropy of 64-bin histogram of |u|/max ----
    if (tid < NXX) out[tid] = ub2[cur][tid].x;

    if (tid == 0) {
        float s2 = 0.0f, vmax = 0.0f;
        for (int i = 0; i < NXX; i++) {
            float u = ub2[cur][i].x;
            s2 += u * u;
            vmax = fmaxf(vmax, fabsf(u));
        }
        float phi2 = s2 * (1.0f / 64.0f);

        int hist[64];
#pragma unroll
        for (int i = 0; i < 64; i++) hist[i] = 0;
        float denom = fmaxf(vmax, 1e-12f);
        for (int i = 0; i < NXX; i++) {
            float vn = fabsf(ub2[cur][i].x) / denom;   // IEEE div, matches ref
            int b = (int)(vn * 64.0f);
            if (b > 63) b = 63;
            hist[b]++;
        }
        float H = 0.0f;
        for (int i = 0; i < 64; i++) {
            if (hist[i] > 0) {
                float pb = (float)hist[i] * (1.0f / 64.0f);
                H -= pb * logf(pb);
            }
        }
        if (vmax < 1e-12f) H = 0.0f;
        out[64] = phi2;
        out[65] = H;
    }
}

extern "C" void kernel_launch(void* const* d_in, const int* in_sizes, int n_in,
                              void* d_out, int out_size) {
    (void)in_sizes; (void)n_in; (void)out_size;
    scct_kernel<<<1, 128>>>(
        (const float*)d_in[0],  // u0
        (const float*)d_in[1],  // w1
        (const float*)d_in[2],  // b1
        (const float*)d_in[3],  // w2
        (const float*)d_in[4],  // b2
        (const float*)d_in[5],  // wc
        (const float*)d_in[6],  // bc
        (const float*)d_in[7],  // gamma
        (const int*)  d_in[8],  // Nt
        (float*)d_out);
}

// round 8
// speedup vs baseline: 1.0602x; 1.0602x over previous
#include <cuda_runtime.h>
#include <cstdint>

#define NXX 64
#define DTT 1e-4f

__device__ __forceinline__ float tanh_approx(float x) {
    float t;
    asm("tanh.approx.f32 %0, %1;" : "=f"(t) : "f"(x));
    return t;
}
__device__ __forceinline__ uint64_t pack2(float lo, float hi) {
    uint64_t r;
    asm("mov.b64 %0, {%1, %2};" : "=l"(r) : "f"(lo), "f"(hi));
    return r;
}
__device__ __forceinline__ void unpack2(uint64_t v, float& lo, float& hi) {
    asm("mov.b64 {%0, %1}, %2;" : "=f"(lo), "=f"(hi) : "l"(v));
}
__device__ __forceinline__ uint64_t fma2(uint64_t a, uint64_t b, uint64_t c) {
    uint64_t d;
    asm("fma.rn.f32x2 %0, %1, %2, %3;" : "=l"(d) : "l"(a), "l"(b), "l"(c));
    return d;
}
__device__ __forceinline__ uint64_t add2(uint64_t a, uint64_t b) {
    uint64_t d;
    asm("add.rn.f32x2 %0, %1, %2;" : "=l"(d) : "l"(a), "l"(b));
    return d;
}

// 128 threads: 2 lanes per grid point (p = tid>>1, s = tid&1).
// Lane s owns one full 16-unit layer, processed as 8 f32x2 PAIRS (FFMA2).
// Stencil folded into weights: z = Wp*up + Wm*um + zb,
//   Wp = 31.5*Wg + 3969*Wl, Wm = -31.5*Wg + 3969*Wl, Wuc = Wu - 7938*Wl
// (f64 folds at init; boundary lanes: Wp=Wm=0, Wuc=Wu).
// State DUPLICATED as float2 (u,u) and loaded as uint64_t: one LDS.64 lands
// directly in the register pair consumed by fma.rn.f32x2 (no pack movs).
// Loop order per step: LDS FIRST (chain head, 29-cyc latency), then the
// zb/cb shadow (register-only, executes inside the LDS shadow), then z.
// This removes the shadow from the pre-barrier arrival path (R6) without
// delaying the LDS (R7's mistake).
// Head fully folded: Cq = gamma*DT*wc; un = uc + DT*core + gamma*DT*bc + P.
__global__ __launch_bounds__(128, 1) void scct_kernel(
    const float* __restrict__ u0,  const float* __restrict__ w1,
    const float* __restrict__ b1,  const float* __restrict__ w2,
    const float* __restrict__ b2,  const float* __restrict__ wc,
    const float* __restrict__ bc,  const float* __restrict__ gamma_p,
    const int*   __restrict__ nt_p, float* __restrict__ out)
{
    __shared__ float2 ub2[2][NXX];

    const int tid = threadIdx.x;
    const int p = tid >> 1;   // grid point 0..63
    const int s = tid & 1;    // layer select

    const float* wsel = s ? w2 : w1;
    const float* bsel = s ? b2 : b1;

    const float gmm = *gamma_p;
    const float gdt = gmm * DTT;
    const bool interior = (p > 0) && (p < NXX - 1);

    uint64_t Wp2[8], Wm2[8], Wuc2[8], Bq2[8], Cq2[8];
#pragma unroll
    for (int j = 0; j < 8; j++) {
        float pl[2], ml[2], ul[2], bl[2], cl[2];
#pragma unroll
        for (int h = 0; h < 2; h++) {
            int q = 2 * j + h;
            double Wu = (double)wsel[q * 3 + 0];
            double Wg = (double)wsel[q * 3 + 1];
            double Wl = (double)wsel[q * 3 + 2];
            if (interior) {
                pl[h] = (float)( 31.5 * Wg + 3969.0 * Wl);
                ml[h] = (float)(-31.5 * Wg + 3969.0 * Wl);
                ul[h] = (float)(Wu - 7938.0 * Wl);
            } else {
                pl[h] = 0.0f;
                ml[h] = 0.0f;
                ul[h] = (float)Wu;
            }
            bl[h] = bsel[q];
            cl[h] = gdt * wc[s * 16 + q];
        }
        Wp2[j]  = pack2(pl[0], pl[1]);
        Wm2[j]  = pack2(ml[0], ml[1]);
        Wuc2[j] = pack2(ul[0], ul[1]);
        Bq2[j]  = pack2(bl[0], bl[1]);
        Cq2[j]  = pack2(cl[0], cl[1]);
    }
    const float Kc = gdt * (*bc);
    const int Nt = *nt_p;

    if (tid < NXX) {
        float v = u0[tid];
        ub2[0][tid] = make_float2(v, v);
    }
    __syncthreads();

    const float INVDX2 = 3969.0f;  // 63^2

    const int pm = (p == 0) ? 0 : p - 1;
    const int pp = (p == NXX - 1) ? NXX - 1 : p + 1;

    float uc = ub2[0][p].x;
    int cur = 0;

    for (int it = 0; it < Nt; ++it) {
        // ---- chain head: LDS.64 issues FIRST (29-cyc latency) ----
        const uint64_t um2 = *reinterpret_cast<const uint64_t*>(&ub2[cur][pm]);
        const uint64_t up2 = *reinterpret_cast<const uint64_t*>(&ub2[cur][pp]);

        // ---- shadow: register-only, fills the LDS latency window ----
        uint64_t zb2[8];
        {
            const uint64_t uc2 = pack2(uc, uc);
#pragma unroll
            for (int j = 0; j < 8; j++) zb2[j] = fma2(Wuc2[j], uc2, Bq2[j]);
        }
        const float cb = fmaf(0.5f, uc, -(uc * uc * uc));   // 0.5u - u^3

        // ---- MLP: 8 f32x2 pairs, 2 independent acc chains ----
        uint64_t A0 = 0ull, A1 = 0ull;
#pragma unroll
        for (int j = 0; j < 8; j++) {
            uint64_t z2 = fma2(Wp2[j], up2, fma2(Wm2[j], um2, zb2[j]));
            float zl, zh;
            unpack2(z2, zl, zh);
            uint64_t t2 = pack2(tanh_approx(zl), tanh_approx(zh));
            if (j & 1) A1 = fma2(Cq2[j], t2, A1);
            else       A0 = fma2(Cq2[j], t2, A0);
        }
        float al, ah;
        unpack2(add2(A0, A1), al, ah);
        float P = al + ah;
        P += __shfl_xor_sync(0xffffffffu, P, 1);   // both lanes: full head sum

        // core/base overlap the shfl (scalar um/up from pair low halves)
        float um, up, dumm;
        unpack2(um2, um, dumm);
        unpack2(up2, up, dumm);
        const float lx   = ((up - 2.0f * uc) + um) * INVDX2;
        const float core = fmaf(0.8f, lx, cb);
        const float base = fmaf(DTT, core, uc) + Kc;

        float un = base + P;
        un = interior ? un : 0.0f;

        if (s == 0) ub2[cur ^ 1][p] = make_float2(un, un);
        __syncthreads();

        uc = un;
        cur ^= 1;
    }

    // ---- epilogue: u, phi2, entropy of 64-bin histogram of |u|/max ----
    if (tid < NXX) out[tid] = ub2[cur][tid].x;

    if (tid == 0) {
        float s2 = 0.0f, vmax = 0.0f;
        for (int i = 0; i < NXX; i++) {
            float u = ub2[cur][i].x;
            s2 += u * u;
            vmax = fmaxf(vmax, fabsf(u));
        }
        float phi2 = s2 * (1.0f / 64.0f);

        int hist[64];
#pragma unroll
        for (int i = 0; i < 64; i++) hist[i] = 0;
        float denom = fmaxf(vmax, 1e-12f);
        for (int i = 0; i < NXX; i++) {
            float vn = fabsf(ub2[cur][i].x) / denom;   // IEEE div, matches ref
            int b = (int)(vn * 64.0f);
            if (b > 63) b = 63;
            hist[b]++;
        }
        float H = 0.0f;
        for (int i = 0; i < 64; i++) {
            if (hist[i] > 0) {
                float pb = (float)hist[i] * (1.0f / 64.0f);
                H -= pb * logf(pb);
            }
        }
        if (vmax < 1e-12f) H = 0.0f;
        out[64] = phi2;
        out[65] = H;
    }
}

extern "C" void kernel_launch(void* const* d_in, const int* in_sizes, int n_in,
                              void* d_out, int out_size) {
    (void)in_sizes; (void)n_in; (void)out_size;
    scct_kernel<<<1, 128>>>(
        (const float*)d_in[0],  // u0
        (const float*)d_in[1],  // w1
        (const float*)d_in[2],  // b1
        (const float*)d_in[3],  // w2
        (const float*)d_in[4],  // b2
        (const float*)d_in[5],  // wc
        (const float*)d_in[6],  // bc
        (const float*)d_in[7],  // gamma
        (const int*)  d_in[8],  // Nt
        (float*)d_out);
}